// round 5
// baseline (speedup 1.0000x reference)
#include <cuda_runtime.h>

#define B_ 16
#define C_ 512
#define N_ 4096
#define K_ 32
#define CW_PITCH 36   // smem pitch for transposed codewords: 36%32=4 -> 4-way write conflict only, 16B-aligned rows

// 8 MB scratch for softmax weights w[b][n][k]
__device__ __align__(16) float g_w[B_ * N_ * K_];

// ---------------- packed f32x2 helpers ----------------
__device__ __forceinline__ unsigned long long pk2(float a, float b) {
    unsigned long long r;
    asm("mov.b64 %0, {%1, %2};" : "=l"(r) : "f"(a), "f"(b));
    return r;
}
__device__ __forceinline__ void ffma2(unsigned long long &d, unsigned long long a, unsigned long long b) {
    asm("fma.rn.f32x2 %0, %1, %2, %0;" : "+l"(d) : "l"(a), "l"(b));
}
__device__ __forceinline__ void upk2(unsigned long long v, float &a, float &b) {
    asm("mov.b64 {%0, %1}, %2;" : "=f"(a), "=f"(b) : "l"(v));
}
__device__ __forceinline__ void lds_v2_u64(unsigned addr, unsigned long long &a, unsigned long long &b) {
    asm volatile("ld.shared.v2.b64 {%0, %1}, [%2];" : "=l"(a), "=l"(b) : "r"(addr));
}

// ---------------- kernel 0: zero the output ----------------
__global__ void zero_kernel(float *out) {
    int i = blockIdx.x * 256 + threadIdx.x;
    out[i] = 0.0f;
}

// ---------------- kernel 1: xc gemm + softmax -> g_w ----------------
// One thread = one token. grid = B*N/128 = 512 blocks of 128 threads.
// dyn smem: cwT[512][36] + sa[32] + sd[32]  (~74 KB)
__global__ void __launch_bounds__(128) assign_kernel(const float *__restrict__ x,
                                                     const float *__restrict__ cw,
                                                     const float *__restrict__ scale) {
    extern __shared__ float sm[];
    float *cwT = sm;                          // [C_][CW_PITCH], k contiguous
    float *sa = sm + C_ * CW_PITCH;           // scale[k]
    float *sd = sa + K_;                      // scale[k]*csq[k]
    const int tid = threadIdx.x;

    // load codewords transposed: cwT[c][k] = cw[k][c]
    for (int i = tid; i < K_ * C_; i += 128) {
        int k = i >> 9;
        int c = i & (C_ - 1);
        cwT[c * CW_PITCH + k] = cw[i];
    }
    __syncthreads();
    if (tid < K_) {
        float s = 0.0f;
        for (int c = 0; c < C_; ++c) {
            float v = cwT[c * CW_PITCH + tid];
            s = fmaf(v, v, s);
        }
        float sc = scale[tid];
        sa[tid] = sc;
        sd[tid] = sc * s;
    }
    __syncthreads();

    const int g = blockIdx.x * 128 + tid;                       // global token id = b*4096 + n
    const float *xp = x + (size_t)(g >> 12) * (C_ * (size_t)N_) + (size_t)(g & (N_ - 1));

    unsigned long long acc[16];                                 // acc[m] = xc pair (k=2m, 2m+1)
#pragma unroll
    for (int m = 0; m < 16; ++m) acc[m] = 0ull;
    float xsq = 0.0f;
    const unsigned cwb = (unsigned)__cvta_generic_to_shared(cwT);

#pragma unroll 1
    for (int c = 0; c < C_; c += 8) {
        float xv[8];
#pragma unroll
        for (int u = 0; u < 8; ++u) xv[u] = xp[(size_t)(c + u) * N_];   // coalesced 128B/warp, MLP=8
#pragma unroll
        for (int u = 0; u < 8; ++u) {
            float v = xv[u];
            xsq = fmaf(v, v, xsq);
            unsigned long long xx = pk2(v, v);
            unsigned rowa = cwb + (unsigned)(c + u) * (CW_PITCH * 4);
#pragma unroll
            for (int j = 0; j < 8; ++j) {                       // 32 k = 8 x 16B, broadcast reads
                unsigned long long w0, w1;
                lds_v2_u64(rowa + j * 16u, w0, w1);
                ffma2(acc[2 * j], xx, w0);
                ffma2(acc[2 * j + 1], xx, w1);
            }
        }
    }

    // softmax over k
    float l[K_];
#pragma unroll
    for (int m = 0; m < 16; ++m) {
        float a, b;
        upk2(acc[m], a, b);
        l[2 * m] = a;
        l[2 * m + 1] = b;
    }
    float mx = -1e30f;
#pragma unroll
    for (int k = 0; k < K_; ++k) {
        float lv = sa[k] * (xsq - 2.0f * l[k]) + sd[k];         // scale*(xsq + csq - 2xc)
        l[k] = lv;
        mx = fmaxf(mx, lv);
    }
    float s = 0.0f;
#pragma unroll
    for (int k = 0; k < K_; ++k) {
        float e = __expf(l[k] - mx);
        l[k] = e;
        s += e;
    }
    float inv = 1.0f / s;
    float *wp = g_w + (size_t)g * K_;
#pragma unroll
    for (int k = 0; k < K_; k += 4) {
        float4 v = make_float4(l[k] * inv, l[k + 1] * inv, l[k + 2] * inv, l[k + 3] * inv);
        *reinterpret_cast<float4 *>(wp + k) = v;
    }
}

// ---------------- kernel 2: aggregate ----------------
// grid = (N/256 n-splits, B) = (16,16) = 256 blocks, 256 threads.
// Thread owns c-pair (c=2*tid, 2*tid+1) x all 32 k. w chunk in smem (broadcast),
// x streamed via float4 (each element read exactly once), red.global at the end.
__global__ void __launch_bounds__(256, 2) aggregate_kernel(const float *__restrict__ x,
                                                           const float *__restrict__ cw,
                                                           float *__restrict__ out) {
    __shared__ __align__(16) float ws[128 * K_];   // 16 KB: w chunk [i][k]
    __shared__ float part[256];
    __shared__ float wsf[K_];

    const int tid = threadIdx.x;
    const int b = blockIdx.y;
    const int n0 = blockIdx.x * 256;
    const int cl = tid * 2;
    const int kw = tid & 31;
    const int p = tid >> 5;

    unsigned long long acc[32];   // acc[m]: (k=2m,2m+1) for c=cl ; acc[16+m]: same for c=cl+1
#pragma unroll
    for (int m = 0; m < 32; ++m) acc[m] = 0ull;
    float lws = 0.0f;
    const unsigned wsb = (unsigned)__cvta_generic_to_shared(ws);

    for (int ch = 0; ch < 2; ++ch) {
        const int nb = n0 + ch * 128;
        __syncthreads();   // protect ws against overwrite (2nd chunk)
        const float4 *gw4 = reinterpret_cast<const float4 *>(g_w + ((size_t)b * N_ + nb) * K_);
        float4 *ws4 = reinterpret_cast<float4 *>(ws);
#pragma unroll
        for (int j = 0; j < 4; ++j) ws4[tid + 256 * j] = gw4[tid + 256 * j];
        __syncthreads();

        const float4 *xra4 = reinterpret_cast<const float4 *>(x + ((size_t)b * C_ + cl) * N_ + nb);
        const float4 *xrb4 = reinterpret_cast<const float4 *>(x + ((size_t)b * C_ + cl + 1) * N_ + nb);

        float4 va = xra4[0];
        float4 vb = xrb4[0];
#pragma unroll 1
        for (int g4 = 0; g4 < 32; ++g4) {
            int g4n = (g4 + 1 < 32) ? g4 + 1 : 31;
            float4 na = xra4[g4n];            // prefetch next group
            float4 nb2 = xrb4[g4n];
            const float xa[4] = {va.x, va.y, va.z, va.w};
            const float xb[4] = {vb.x, vb.y, vb.z, vb.w};
#pragma unroll
            for (int u = 0; u < 4; ++u) {
                const int i = g4 * 4 + u;
                unsigned long long xxa = pk2(xa[u], xa[u]);
                unsigned long long xxb = pk2(xb[u], xb[u]);
                unsigned rowa = wsb + (unsigned)i * (K_ * 4);
#pragma unroll
                for (int j = 0; j < 8; ++j) {   // broadcast: all lanes same address
                    unsigned long long w0, w1;
                    lds_v2_u64(rowa + j * 16u, w0, w1);
                    ffma2(acc[2 * j], xxa, w0);
                    ffma2(acc[2 * j + 1], xxa, w1);
                    ffma2(acc[16 + 2 * j], xxb, w0);
                    ffma2(acc[16 + 2 * j + 1], xxb, w1);
                }
            }
            va = na;
            vb = nb2;
        }
        // wsum partial: thread (p,kw) sums i = p + 8*j
#pragma unroll
        for (int j = 0; j < 16; ++j) lws += ws[(p + 8 * j) * K_ + kw];
    }

    part[tid] = lws;   // tid == p*32 + kw
    __syncthreads();
    if (tid < K_) {
        float s = 0.0f;
#pragma unroll
        for (int q = 0; q < 8; ++q) s += part[q * 32 + tid];
        wsf[tid] = s;
    }
    __syncthreads();

    float *ob = out + (size_t)b * K_ * C_;
#pragma unroll
    for (int m = 0; m < 16; ++m) {
        const int k = 2 * m;
        float a0, a1, b0, b1;
        upk2(acc[m], a0, a1);          // a0: (k, cl)   a1: (k+1, cl)
        upk2(acc[16 + m], b0, b1);     // b0: (k, cl+1) b1: (k+1, cl+1)
        float wk0 = wsf[k];
        float wk1 = wsf[k + 1];
        float2 cw0 = *reinterpret_cast<const float2 *>(&cw[(size_t)k * C_ + cl]);
        float2 cw1 = *reinterpret_cast<const float2 *>(&cw[(size_t)(k + 1) * C_ + cl]);
        atomicAdd(&ob[(size_t)k * C_ + cl], a0 - wk0 * cw0.x);
        atomicAdd(&ob[(size_t)k * C_ + cl + 1], b0 - wk0 * cw0.y);
        atomicAdd(&ob[(size_t)(k + 1) * C_ + cl], a1 - wk1 * cw1.x);
        atomicAdd(&ob[(size_t)(k + 1) * C_ + cl + 1], b1 - wk1 * cw1.y);
    }
}

extern "C" void kernel_launch(void *const *d_in, const int *in_sizes, int n_in,
                              void *d_out, int out_size) {
    const float *x = (const float *)d_in[0];
    const float *cwp = (const float *)d_in[1];
    const float *scale = (const float *)d_in[2];
    float *out = (float *)d_out;

    const int smem1 = (C_ * CW_PITCH + 2 * K_) * (int)sizeof(float);   // ~74 KB
    cudaFuncSetAttribute(assign_kernel, cudaFuncAttributeMaxDynamicSharedMemorySize, smem1);

    zero_kernel<<<(B_ * K_ * C_) / 256, 256>>>(out);
    assign_kernel<<<(B_ * N_) / 128, 128, smem1>>>(x, cwp, scale);
    aggregate_kernel<<<dim3(N_ / 256, B_), 256>>>(x, cwp, out);
}

// round 6
// speedup vs baseline: 1.4025x; 1.4025x over previous
#include <cuda_runtime.h>

#define B_ 16
#define C_ 512
#define N_ 4096
#define K_ 32
#define CW_PITCH 36      // assign: smem pitch for transposed codewords (16B-aligned rows)

#define AGG_NC 128       // aggregate: n-chunk per block
#define AGG_NS 16        // aggregate: n per staged subtile
#define XS_PITCH 258     // aggregate: xs row pitch in floats (256 c + 2 pad, even for LDS.64 align)

// 8 MB scratch for softmax weights w[b][n][k]
__device__ __align__(16) float g_w[B_ * N_ * K_];

// ---------------- packed f32x2 helpers ----------------
__device__ __forceinline__ unsigned long long pk2(float a, float b) {
    unsigned long long r;
    asm("mov.b64 %0, {%1, %2};" : "=l"(r) : "f"(a), "f"(b));
    return r;
}
__device__ __forceinline__ void ffma2(unsigned long long &d, unsigned long long a, unsigned long long b) {
    asm("fma.rn.f32x2 %0, %1, %2, %0;" : "+l"(d) : "l"(a), "l"(b));
}
__device__ __forceinline__ void upk2(unsigned long long v, float &a, float &b) {
    asm("mov.b64 {%0, %1}, %2;" : "=f"(a), "=f"(b) : "l"(v));
}
__device__ __forceinline__ void lds_v2_u64(unsigned addr, unsigned long long &a, unsigned long long &b) {
    asm volatile("ld.shared.v2.b64 {%0, %1}, [%2];" : "=l"(a), "=l"(b) : "r"(addr));
}
__device__ __forceinline__ unsigned long long lds_u64(unsigned addr) {
    unsigned long long v;
    asm volatile("ld.shared.b64 %0, [%1];" : "=l"(v) : "r"(addr));
    return v;
}

// ---------------- kernel 1: xc gemm + softmax -> g_w (also zeroes out) ----------------
// One thread = one token. grid = B*N/128 = 512 blocks of 128 threads.
__global__ void __launch_bounds__(128) assign_kernel(const float *__restrict__ x,
                                                     const float *__restrict__ cw,
                                                     const float *__restrict__ scale,
                                                     float *__restrict__ out) {
    extern __shared__ float sm[];
    float *cwT = sm;                          // [C_][CW_PITCH], k contiguous
    float *sa = sm + C_ * CW_PITCH;           // scale[k]
    float *sd = sa + K_;                      // scale[k]*csq[k]
    const int tid = threadIdx.x;

    // fold the output-zeroing pass in here (512 blocks * 128 threads * float4 = 262144 floats)
    reinterpret_cast<float4 *>(out)[blockIdx.x * 128 + tid] = make_float4(0.f, 0.f, 0.f, 0.f);

    // load codewords transposed: cwT[c][k] = cw[k][c]
    for (int i = tid; i < K_ * C_; i += 128) {
        int k = i >> 9;
        int c = i & (C_ - 1);
        cwT[c * CW_PITCH + k] = cw[i];
    }
    __syncthreads();
    if (tid < K_) {
        float s = 0.0f;
        for (int c = 0; c < C_; ++c) {
            float v = cwT[c * CW_PITCH + tid];
            s = fmaf(v, v, s);
        }
        float sc = scale[tid];
        sa[tid] = sc;
        sd[tid] = sc * s;
    }
    __syncthreads();

    const int g = blockIdx.x * 128 + tid;                       // global token id = b*4096 + n
    const float *xp = x + (size_t)(g >> 12) * (C_ * (size_t)N_) + (size_t)(g & (N_ - 1));

    unsigned long long acc[16];                                 // acc[m] = xc pair (k=2m, 2m+1)
#pragma unroll
    for (int m = 0; m < 16; ++m) acc[m] = 0ull;
    float xsq = 0.0f;
    const unsigned cwb = (unsigned)__cvta_generic_to_shared(cwT);

#pragma unroll 1
    for (int c = 0; c < C_; c += 8) {
        float xv[8];
#pragma unroll
        for (int u = 0; u < 8; ++u) xv[u] = xp[(size_t)(c + u) * N_];   // coalesced, MLP=8
#pragma unroll
        for (int u = 0; u < 8; ++u) {
            float v = xv[u];
            xsq = fmaf(v, v, xsq);
            unsigned long long xx = pk2(v, v);
            unsigned rowa = cwb + (unsigned)(c + u) * (CW_PITCH * 4);
#pragma unroll
            for (int j = 0; j < 8; ++j) {                       // broadcast reads: all lanes same addr
                unsigned long long w0, w1;
                lds_v2_u64(rowa + j * 16u, w0, w1);
                ffma2(acc[2 * j], xx, w0);
                ffma2(acc[2 * j + 1], xx, w1);
            }
        }
    }

    // softmax over k
    float l[K_];
#pragma unroll
    for (int m = 0; m < 16; ++m) {
        float a, b;
        upk2(acc[m], a, b);
        l[2 * m] = a;
        l[2 * m + 1] = b;
    }
    float mx = -1e30f;
#pragma unroll
    for (int k = 0; k < K_; ++k) {
        float lv = sa[k] * (xsq - 2.0f * l[k]) + sd[k];         // scale*(xsq + csq - 2xc)
        l[k] = lv;
        mx = fmaxf(mx, lv);
    }
    float s = 0.0f;
#pragma unroll
    for (int k = 0; k < K_; ++k) {
        float e = __expf(l[k] - mx);
        l[k] = e;
        s += e;
    }
    float inv = 1.0f / s;
    float *wp = g_w + (size_t)g * K_;
#pragma unroll
    for (int k = 0; k < K_; k += 4) {
        float4 v = make_float4(l[k] * inv, l[k + 1] * inv, l[k + 2] * inv, l[k + 3] * inv);
        *reinterpret_cast<float4 *>(wp + k) = v;
    }
}

// ---------------- kernel 2: aggregate ----------------
// grid = (N/128, B, 2 c-halves) = (32, 16, 2) = 1024 blocks of 128 threads.
// x staged through smem TRANSPOSED (xs[n][c]) so both the global read (coalesced
// along n) and the compute read (lane-consecutive c via LDS.64) are clean.
// Thread owns c-pair (within its 256-c half) x all 32 k = 32 packed accumulators.
__global__ void __launch_bounds__(128) aggregate_kernel(const float *__restrict__ x,
                                                        const float *__restrict__ cw,
                                                        float *__restrict__ out) {
    __shared__ __align__(16) float ws[AGG_NC * K_];          // 16 KB: w rows [i][32k]
    __shared__ __align__(16) float xs[AGG_NS * XS_PITCH];    // ~16.5 KB: x subtile [n][256c]
    __shared__ float part[128];
    __shared__ float wsf[K_];

    const int tid = threadIdx.x;
    const int b = blockIdx.y;
    const int n0 = blockIdx.x * AGG_NC;
    const int ch = blockIdx.z;          // c-half
    const int cbase = ch * 256;         // global c offset of this block's half
    const int c0l = 2 * tid;            // local c (0..255) pair owned by this thread

    // load w chunk [AGG_NC][32] (coalesced float4)
    {
        const float4 *gw4 = reinterpret_cast<const float4 *>(g_w + ((size_t)b * N_ + n0) * K_);
        float4 *ws4 = reinterpret_cast<float4 *>(ws);
#pragma unroll
        for (int j = 0; j < 8; ++j) ws4[tid + 128 * j] = gw4[tid + 128 * j];
    }

    unsigned long long acc[32];   // acc[m] -> (c0l, k=2m..); acc[16+m] -> (c0l+1, ...)
#pragma unroll
    for (int m = 0; m < 32; ++m) acc[m] = 0ull;

    const unsigned wsb = (unsigned)__cvta_generic_to_shared(ws);
    const unsigned xsb = (unsigned)__cvta_generic_to_shared(xs);
    const float *xg = x + ((size_t)b * C_ + cbase) * N_ + n0;

#pragma unroll 1
    for (int s = 0; s < AGG_NC / AGG_NS; ++s) {
        __syncthreads();   // xs free to overwrite (also orders ws load on s==0)
        // stage subtile: 256 c x 16 n -> xs[n][c], 8 float4 per thread
#pragma unroll
        for (int j = 0; j < 8; ++j) {
            int flat = tid + 128 * j;        // 0..1023
            int c = flat >> 2;               // local c 0..255
            int q = flat & 3;                // n-quad within subtile
            float4 v = *reinterpret_cast<const float4 *>(xg + (size_t)c * N_ + s * AGG_NS + 4 * q);
            int nb = 4 * q;
            xs[(nb + 0) * XS_PITCH + c] = v.x;   // STS banks verified conflict-free
            xs[(nb + 1) * XS_PITCH + c] = v.y;
            xs[(nb + 2) * XS_PITCH + c] = v.z;
            xs[(nb + 3) * XS_PITCH + c] = v.w;
        }
        __syncthreads();

#pragma unroll 2
        for (int ii = 0; ii < AGG_NS; ++ii) {
            const int i = s * AGG_NS + ii;
            unsigned long long xpair = lds_u64(xsb + (unsigned)((ii * XS_PITCH + c0l) * 4));
            float x0, x1;
            upk2(xpair, x0, x1);
            unsigned long long xx0 = pk2(x0, x0);
            unsigned long long xx1 = pk2(x1, x1);
            unsigned rowa = wsb + (unsigned)i * (K_ * 4);
#pragma unroll
            for (int j = 0; j < 8; ++j) {      // broadcast w reads
                unsigned long long w0, w1;
                lds_v2_u64(rowa + j * 16u, w0, w1);
                ffma2(acc[2 * j], xx0, w0);
                ffma2(acc[2 * j + 1], xx0, w1);
                ffma2(acc[16 + 2 * j], xx1, w0);
                ffma2(acc[16 + 2 * j + 1], xx1, w1);
            }
        }
    }

    // per-block wsum over this n-chunk (conflict-free: bank = k)
    {
        float lws = 0.0f;
        const int kk = tid & 31;
        const int r = tid >> 5;   // 0..3
#pragma unroll
        for (int j = 0; j < 32; ++j) lws += ws[(r + 4 * j) * K_ + kk];
        part[tid] = lws;
    }
    __syncthreads();
    if (tid < K_) {
        float s = 0.0f;
#pragma unroll
        for (int q = 0; q < 4; ++q) s += part[tid + 32 * q];
        wsf[tid] = s;
    }
    __syncthreads();

    // epilogue: fold -wsum*cw locally, reduce to global (coalesced red.global.f32)
    const int cg = cbase + c0l;
    float *ob = out + (size_t)b * K_ * C_;
#pragma unroll
    for (int m = 0; m < 16; ++m) {
        const int k = 2 * m;
        float a0, a1, b0, b1;
        upk2(acc[m], a0, a1);          // a0:(k,cg)   a1:(k+1,cg)
        upk2(acc[16 + m], b0, b1);     // b0:(k,cg+1) b1:(k+1,cg+1)
        float wk0 = wsf[k];
        float wk1 = wsf[k + 1];
        float2 cw0 = *reinterpret_cast<const float2 *>(&cw[(size_t)k * C_ + cg]);
        float2 cw1 = *reinterpret_cast<const float2 *>(&cw[(size_t)(k + 1) * C_ + cg]);
        atomicAdd(&ob[(size_t)k * C_ + cg], a0 - wk0 * cw0.x);
        atomicAdd(&ob[(size_t)k * C_ + cg + 1], b0 - wk0 * cw0.y);
        atomicAdd(&ob[(size_t)(k + 1) * C_ + cg], a1 - wk1 * cw1.x);
        atomicAdd(&ob[(size_t)(k + 1) * C_ + cg + 1], b1 - wk1 * cw1.y);
    }
}

extern "C" void kernel_launch(void *const *d_in, const int *in_sizes, int n_in,
                              void *d_out, int out_size) {
    const float *x = (const float *)d_in[0];
    const float *cwp = (const float *)d_in[1];
    const float *scale = (const float *)d_in[2];
    float *out = (float *)d_out;

    const int smem1 = (C_ * CW_PITCH + 2 * K_) * (int)sizeof(float);   // ~74 KB
    cudaFuncSetAttribute(assign_kernel, cudaFuncAttributeMaxDynamicSharedMemorySize, smem1);

    assign_kernel<<<(B_ * N_) / 128, 128, smem1>>>(x, cwp, scale, out);
    aggregate_kernel<<<dim3(N_ / AGG_NC, B_, 2), 128>>>(x, cwp, out);
}

// round 8
// speedup vs baseline: 2.5572x; 1.8233x over previous
#include <cuda_runtime.h>

#define B_ 16
#define C_ 512
#define N_ 4096
#define K_ 32

// 8 MB scratch for softmax weights w[b][n][k]
__device__ __align__(16) float g_w[B_ * N_ * K_];

typedef unsigned long long ull;

// ---------------- packed f32x2 helpers ----------------
__device__ __forceinline__ ull pk2(float a, float b) {
    ull r;
    asm("mov.b64 %0, {%1, %2};" : "=l"(r) : "f"(a), "f"(b));
    return r;
}
__device__ __forceinline__ void ffma2(ull &d, ull a, ull b) {
    asm("fma.rn.f32x2 %0, %1, %2, %0;" : "+l"(d) : "l"(a), "l"(b));
}
__device__ __forceinline__ void upk2(ull v, float &a, float &b) {
    asm("mov.b64 {%0, %1}, %2;" : "=f"(a), "=f"(b) : "l"(v));
}
__device__ __forceinline__ ull lds_u64(unsigned addr) {
    ull v;
    asm volatile("ld.shared.b64 %0, [%1];" : "=l"(v) : "r"(addr));
    return v;
}

// ================= kernel 1: assign (xc gemm + softmax -> g_w, zeroes out) ==============
// 256 tokens/block, 128 threads = 32 lane n-groups x 4 warp k-groups.
// Thread tile: 8 tokens (4 n-pairs at {64j+2L}) x 8 k (8*kg..). acc packed over n-pairs.
// smem word layout:
//   [0,8448)      xs[c 0..31][n 0..255] (chunk)  |  later: sxc[tok 0..255][k, pitch 33]
//   [8448,9600)   cws[c 0..31][k, pitch 36]
//   [9600,9856)   sqA[256]   [9856,10112) sqB[256]
//   [10112,10144) sa[32]     [10144,10176) sd[32]
#define XSA 0
#define CWSA 8448
#define SQA 9600
#define SQB 9856
#define SAO 10112
#define SDO 10144
#define ASM_WORDS 10176

__global__ void __launch_bounds__(128) assign_kernel(const float *__restrict__ x,
                                                     const float *__restrict__ cw,
                                                     const float *__restrict__ scale,
                                                     float *__restrict__ out) {
    __shared__ __align__(16) float sm[ASM_WORDS];
    const int t = threadIdx.x;

    // fold output zeroing (out poisoned by harness): 256 blocks * 128 thr * 2 float4 = 262144 floats
    {
        float4 z = make_float4(0.f, 0.f, 0.f, 0.f);
        reinterpret_cast<float4 *>(out)[blockIdx.x * 256 + t] = z;
        reinterpret_cast<float4 *>(out)[blockIdx.x * 256 + 128 + t] = z;
    }

    const int T0 = blockIdx.x * 256;                    // global token base (within one b)
    const float *xb = x + (size_t)(T0 >> 12) * C_ * N_ + (T0 & (N_ - 1));
    const int L = t & 31;                               // lane = n-group
    const int kg = t >> 5;                              // warp = k-group
    const int nq = t & 63;                              // loader: fixed n-quad (tokens 4nq..4nq+3)
    const int crow = t >> 6;                            // loader: c row parity
    const int kA = t >> 3;                              // cw loader: k row (0..15), also kA+16
    const int c4 = (t & 7) * 4;                         // cw loader: c quad

    ull acc[32];
#pragma unroll
    for (int m = 0; m < 32; ++m) acc[m] = 0ull;
    float4 xsq4 = make_float4(0.f, 0.f, 0.f, 0.f);
    float csq0 = 0.f, csq1 = 0.f;

    const unsigned smb = (unsigned)__cvta_generic_to_shared(sm);

#pragma unroll 1
    for (int cc = 0; cc < C_; cc += 32) {
        __syncthreads();
        // stage x chunk [32 c][256 n] (coalesced, fixed n-quad per thread -> xsq partial)
#pragma unroll
        for (int i = 0; i < 16; ++i) {
            const int cl = crow + 2 * i;
            float4 v = *reinterpret_cast<const float4 *>(xb + (size_t)(cc + cl) * N_ + 4 * nq);
            *reinterpret_cast<float4 *>(&sm[XSA + cl * 256 + 4 * nq]) = v;
            xsq4.x = fmaf(v.x, v.x, xsq4.x);
            xsq4.y = fmaf(v.y, v.y, xsq4.y);
            xsq4.z = fmaf(v.z, v.z, xsq4.z);
            xsq4.w = fmaf(v.w, v.w, xsq4.w);
        }
        // stage cw chunk transposed [32 c][32 k] pitch 36 (+ csq partials, fixed 2 k per thread)
        {
            float4 a = *reinterpret_cast<const float4 *>(cw + (size_t)kA * C_ + cc + c4);
            float4 b = *reinterpret_cast<const float4 *>(cw + (size_t)(kA + 16) * C_ + cc + c4);
            sm[CWSA + (c4 + 0) * 36 + kA] = a.x;
            sm[CWSA + (c4 + 1) * 36 + kA] = a.y;
            sm[CWSA + (c4 + 2) * 36 + kA] = a.z;
            sm[CWSA + (c4 + 3) * 36 + kA] = a.w;
            sm[CWSA + (c4 + 0) * 36 + kA + 16] = b.x;
            sm[CWSA + (c4 + 1) * 36 + kA + 16] = b.y;
            sm[CWSA + (c4 + 2) * 36 + kA + 16] = b.z;
            sm[CWSA + (c4 + 3) * 36 + kA + 16] = b.w;
            csq0 = fmaf(a.x, a.x, csq0); csq0 = fmaf(a.y, a.y, csq0);
            csq0 = fmaf(a.z, a.z, csq0); csq0 = fmaf(a.w, a.w, csq0);
            csq1 = fmaf(b.x, b.x, csq1); csq1 = fmaf(b.y, b.y, csq1);
            csq1 = fmaf(b.z, b.z, csq1); csq1 = fmaf(b.w, b.w, csq1);
        }
        __syncthreads();

#pragma unroll 2
        for (int c = 0; c < 32; ++c) {
            ull xp[4];
#pragma unroll
            for (int j = 0; j < 4; ++j)
                xp[j] = lds_u64(smb + (unsigned)((XSA + c * 256 + 64 * j + 2 * L) * 4));
            const float *wrow = &sm[CWSA + c * 36 + 8 * kg];
#pragma unroll
            for (int kk = 0; kk < 8; ++kk) {
                ull wv = pk2(wrow[kk], wrow[kk]);
                ffma2(acc[0 * 8 + kk], xp[0], wv);
                ffma2(acc[1 * 8 + kk], xp[1], wv);
                ffma2(acc[2 * 8 + kk], xp[2], wv);
                ffma2(acc[3 * 8 + kk], xp[3], wv);
            }
        }
    }
    __syncthreads();   // all mainloop reads of xs done before sxc overwrite

    // exchange xc to sxc[tok][k] pitch 33; write xsq partials; reduce csq -> sa/sd
#pragma unroll
    for (int j = 0; j < 4; ++j) {
        const int tok = 64 * j + 2 * L;
#pragma unroll
        for (int kk = 0; kk < 8; ++kk) {
            float lo, hi;
            upk2(acc[j * 8 + kk], lo, hi);
            sm[XSA + tok * 33 + 8 * kg + kk] = lo;
            sm[XSA + (tok + 1) * 33 + 8 * kg + kk] = hi;
        }
    }
    if (t < 64) *reinterpret_cast<float4 *>(&sm[SQA + 4 * nq]) = xsq4;
    else        *reinterpret_cast<float4 *>(&sm[SQB + 4 * nq]) = xsq4;
    // csq: 8 threads (same kA) hold disjoint c-subsets -> octet shfl reduce
#pragma unroll
    for (int d = 1; d < 8; d <<= 1) {
        csq0 += __shfl_xor_sync(0xffffffffu, csq0, d);
        csq1 += __shfl_xor_sync(0xffffffffu, csq1, d);
    }
    if ((t & 7) == 0) {
        float s0 = scale[kA], s1 = scale[kA + 16];
        sm[SAO + kA] = s0;        sm[SDO + kA] = s0 * csq0;
        sm[SAO + kA + 16] = s1;   sm[SDO + kA + 16] = s1 * csq1;
    }
    __syncthreads();

    // softmax: thread t handles tokens t and t+128, writes w back into sxc rows
#pragma unroll
    for (int h = 0; h < 2; ++h) {
        const int tok = t + 128 * h;
        const float xsq = sm[SQA + tok] + sm[SQB + tok];
        float l[K_];
        float mx = -1e30f;
#pragma unroll
        for (int k = 0; k < K_; ++k) {
            float lv = sm[SAO + k] * (xsq - 2.0f * sm[XSA + tok * 33 + k]) + sm[SDO + k];
            l[k] = lv;
            mx = fmaxf(mx, lv);
        }
        float s = 0.f;
#pragma unroll
        for (int k = 0; k < K_; ++k) {
            float e = __expf(l[k] - mx);
            l[k] = e;
            s += e;
        }
        float inv = 1.0f / s;
#pragma unroll
        for (int k = 0; k < K_; ++k) sm[XSA + tok * 33 + k] = l[k] * inv;
    }
    __syncthreads();

    // coalesced copy sxc -> g_w
    float *gw = g_w + (size_t)T0 * K_;
#pragma unroll
    for (int i = 0; i < 64; ++i) {
        const int f = t + 128 * i;
        gw[f] = sm[XSA + (f >> 5) * 33 + (f & 31)];
    }
}

// ================= kernel 2: aggregate (enc gemm + wsum fold + REDG) ==============
// grid (16 n-splits, 16 b, 2 c-tiles), 128 threads = 32 lane c-groups x 4 warp k-groups.
// Thread tile: 8 c (4 pairs at {64j+2L}) x 8 k. x staged transposed xs[n][c] pitch 258.
// dyn smem words: ws[256][32]=8192 | xs[16][258]=4128 | wpart 512 | wsf 32  -> 12864 w = 51456 B
#define WS0 0
#define XS0 8192
#define WP0 12320
#define WF0 12832
#define AGG_WORDS 12864
#define XP 258

__global__ void __launch_bounds__(128) aggregate_kernel(const float *__restrict__ x,
                                                        const float *__restrict__ cw,
                                                        float *__restrict__ out) {
    extern __shared__ float sg[];
    const int t = threadIdx.x;
    const int b = blockIdx.y;
    const int n0 = blockIdx.x * 256;
    const int cbase = blockIdx.z * 256;
    const int L = t & 31;
    const int kg = t >> 5;

    // stage w chunk [256 n][32 k] + wsum partial (fixed k-quad = t%8 per thread)
    {
        const float4 *gw4 = reinterpret_cast<const float4 *>(g_w + ((size_t)b * N_ + n0) * K_);
        float4 wsum4 = make_float4(0.f, 0.f, 0.f, 0.f);
#pragma unroll
        for (int i = 0; i < 16; ++i) {
            float4 v = gw4[t + 128 * i];
            *reinterpret_cast<float4 *>(&sg[WS0 + 4 * (t + 128 * i)]) = v;
            wsum4.x += v.x; wsum4.y += v.y; wsum4.z += v.z; wsum4.w += v.w;
        }
        *reinterpret_cast<float4 *>(&sg[WP0 + 4 * t]) = wsum4;
    }

    ull acc[32];
#pragma unroll
    for (int m = 0; m < 32; ++m) acc[m] = 0ull;

    const unsigned smb = (unsigned)__cvta_generic_to_shared(sg);
    const float *xg = x + ((size_t)b * C_ + cbase) * N_ + n0;

#pragma unroll 1
    for (int s = 0; s < 16; ++s) {
        __syncthreads();
        // stage x subtile transposed: 256 c x 16 n -> xs[n][c], pitch 258
#pragma unroll
        for (int j = 0; j < 8; ++j) {
            const int flat = t + 128 * j;
            const int c = flat >> 2;
            const int q = flat & 3;
            float4 v = *reinterpret_cast<const float4 *>(xg + (size_t)c * N_ + s * 16 + 4 * q);
            sg[XS0 + (4 * q + 0) * XP + c] = v.x;
            sg[XS0 + (4 * q + 1) * XP + c] = v.y;
            sg[XS0 + (4 * q + 2) * XP + c] = v.z;
            sg[XS0 + (4 * q + 3) * XP + c] = v.w;
        }
        __syncthreads();

#pragma unroll 2
        for (int nn = 0; nn < 16; ++nn) {
            const int n = s * 16 + nn;
            ull xp[4];
#pragma unroll
            for (int j = 0; j < 4; ++j)
                xp[j] = lds_u64(smb + (unsigned)((XS0 + nn * XP + 64 * j + 2 * L) * 4));
            const float *wrow = &sg[WS0 + n * 32 + 8 * kg];
#pragma unroll
            for (int kk = 0; kk < 8; ++kk) {
                ull wv = pk2(wrow[kk], wrow[kk]);
                ffma2(acc[0 * 8 + kk], xp[0], wv);
                ffma2(acc[1 * 8 + kk], xp[1], wv);
                ffma2(acc[2 * 8 + kk], xp[2], wv);
                ffma2(acc[3 * 8 + kk], xp[3], wv);
            }
        }
    }

    // reduce wsum partials: 16 threads per k-quad
    __syncthreads();
    if (t < 8) {
        float4 s4 = make_float4(0.f, 0.f, 0.f, 0.f);
#pragma unroll
        for (int j = 0; j < 16; ++j) {
            float4 v = *reinterpret_cast<const float4 *>(&sg[WP0 + 4 * (t + 8 * j)]);
            s4.x += v.x; s4.y += v.y; s4.z += v.z; s4.w += v.w;
        }
        *reinterpret_cast<float4 *>(&sg[WF0 + 4 * t]) = s4;
    }
    __syncthreads();

    // epilogue: fold -wsum_partial*cw, reduce to global (coalesced-pair red.global.f32)
    float *ob = out + (size_t)b * K_ * C_;
#pragma unroll
    for (int kk = 0; kk < 8; ++kk) {
        const int k = 8 * kg + kk;
        const float wk = sg[WF0 + k];
#pragma unroll
        for (int j = 0; j < 4; ++j) {
            const int c = cbase + 64 * j + 2 * L;
            float a0, a1;
            upk2(acc[j * 8 + kk], a0, a1);
            float2 cv = *reinterpret_cast<const float2 *>(&cw[(size_t)k * C_ + c]);
            atomicAdd(&ob[(size_t)k * C_ + c], a0 - wk * cv.x);
            atomicAdd(&ob[(size_t)k * C_ + c + 1], a1 - wk * cv.y);
        }
    }
}

extern "C" void kernel_launch(void *const *d_in, const int *in_sizes, int n_in,
                              void *d_out, int out_size) {
    const float *x = (const float *)d_in[0];
    const float *cwp = (const float *)d_in[1];
    const float *scale = (const float *)d_in[2];
    float *out = (float *)d_out;

    cudaFuncSetAttribute(aggregate_kernel, cudaFuncAttributeMaxDynamicSharedMemorySize,
                         AGG_WORDS * (int)sizeof(float));

    assign_kernel<<<(B_ * N_) / 256, 128>>>(x, cwp, scale, out);
    aggregate_kernel<<<dim3(N_ / 256, B_, 2), 128, AGG_WORDS * sizeof(float)>>>(x, cwp, out);
}